// round 3
// baseline (speedup 1.0000x reference)
#include <cuda_runtime.h>

#define MAXN 100000
#define MAXE 1600000
#define DIN  128

// Scratch (allocation-free rule: __device__ globals)
__device__ float g_dinv[MAXN];
__device__ float g_bufA[(size_t)MAXN * 128];
__device__ float g_bufB[(size_t)MAXN * 128];
__device__ int   g_src[MAXE];
__device__ int   g_dst[MAXE];
__device__ int   g_is32;

// ---------------------------------------------------------------------------
// Edge index dtype probe + conversion
// ---------------------------------------------------------------------------
__global__ void k_probe_init() { g_is32 = 0; }

// Interpret raw as int64; if any value is out of [0, n), data must be int32.
__global__ void k_probe(const long long* __restrict__ raw, int cnt, int n) {
    int i = blockIdx.x * blockDim.x + threadIdx.x;
    if (i < cnt) {
        long long v = raw[i];
        if (v < 0 || v >= (long long)n) g_is32 = 1;
    }
}

__global__ void k_convert(const void* __restrict__ raw, int e) {
    int i = blockIdx.x * blockDim.x + threadIdx.x;
    if (i >= e) return;
    if (g_is32) {
        const int* p = (const int*)raw;
        g_src[i] = p[i];
        g_dst[i] = p[e + i];
    } else {
        const long long* p = (const long long*)raw;
        g_src[i] = (int)p[i];
        g_dst[i] = (int)p[e + i];
    }
}

// ---------------------------------------------------------------------------
// Degree / normalization
// ---------------------------------------------------------------------------
__global__ void k_init_deg(int n) {
    int i = blockIdx.x * blockDim.x + threadIdx.x;
    if (i < n) g_dinv[i] = 1.0f;   // self loop
}

__global__ void k_count_deg(int e) {
    int i = blockIdx.x * blockDim.x + threadIdx.x;
    if (i < e) atomicAdd(&g_dinv[g_dst[i]], 1.0f);
}

__global__ void k_rsqrt_deg(int n) {
    int i = blockIdx.x * blockDim.x + threadIdx.x;
    if (i < n) g_dinv[i] = rsqrtf(g_dinv[i]);
}

// ---------------------------------------------------------------------------
// GEMM: H = act(X) @ W^T   (X:[n,128], W:[FOUT,128])
// Epilogue also writes OUT = bias + dinv[row]^2 * H  (self-loop init)
// ---------------------------------------------------------------------------
template <int FOUT, bool RELU>
__global__ void __launch_bounds__(256, 2) k_gemm(
    const float* __restrict__ X, const float* __restrict__ W,
    const float* __restrict__ bias,
    float* __restrict__ H, float* __restrict__ OUT, int n)
{
    extern __shared__ float sm[];
    float* Ws = sm;               // [DIN][FOUT]  (W transposed: Ws[k*FOUT+c])
    float* Xs = sm + DIN * FOUT;  // [64][DIN]

    const int tid  = threadIdx.x;
    const int row0 = blockIdx.x * 64;

    // Load W transposed into SMEM
    for (int idx = tid; idx < FOUT * DIN / 4; idx += 256) {
        float4 w = ((const float4*)W)[idx];
        int c = (idx * 4) / DIN, k = (idx * 4) % DIN;
        Ws[(k + 0) * FOUT + c] = w.x;
        Ws[(k + 1) * FOUT + c] = w.y;
        Ws[(k + 2) * FOUT + c] = w.z;
        Ws[(k + 3) * FOUT + c] = w.w;
    }
    // Load X tile (ReLU fused on load)
    for (int idx = tid; idx < 64 * DIN / 4; idx += 256) {
        int r = (idx * 4) / DIN, k = (idx * 4) % DIN;
        int row = row0 + r;
        float4 v = make_float4(0.f, 0.f, 0.f, 0.f);
        if (row < n) {
            v = *(const float4*)&X[(size_t)row * DIN + k];
            if (RELU) {
                v.x = fmaxf(v.x, 0.f); v.y = fmaxf(v.y, 0.f);
                v.z = fmaxf(v.z, 0.f); v.w = fmaxf(v.w, 0.f);
            }
        }
        *(float4*)&Xs[r * DIN + k] = v;
    }
    __syncthreads();

    constexpr int NSEG = FOUT / 64;       // 2 for FOUT=128, 1 for FOUT=64
    const int tx = tid & 15, ty = tid >> 4;
    const int cb = tx * 4;

    float acc[4][NSEG][4];
#pragma unroll
    for (int r = 0; r < 4; r++)
#pragma unroll
        for (int s = 0; s < NSEG; s++)
#pragma unroll
            for (int j = 0; j < 4; j++) acc[r][s][j] = 0.f;

#pragma unroll 2
    for (int k = 0; k < DIN; k += 4) {
        float4 a[4];
#pragma unroll
        for (int r = 0; r < 4; r++)
            a[r] = *(const float4*)&Xs[(ty * 4 + r) * DIN + k];
#pragma unroll
        for (int kk = 0; kk < 4; kk++) {
#pragma unroll
            for (int s = 0; s < NSEG; s++) {
                float4 b = *(const float4*)&Ws[(k + kk) * FOUT + s * 64 + cb];
#pragma unroll
                for (int r = 0; r < 4; r++) {
                    float av = ((const float*)&a[r])[kk];
                    acc[r][s][0] += av * b.x;
                    acc[r][s][1] += av * b.y;
                    acc[r][s][2] += av * b.z;
                    acc[r][s][3] += av * b.w;
                }
            }
        }
    }

#pragma unroll
    for (int r = 0; r < 4; r++) {
        int row = row0 + ty * 4 + r;
        if (row >= n) continue;
        float di = g_dinv[row];
        float sl = di * di;
#pragma unroll
        for (int s = 0; s < NSEG; s++) {
            int c = s * 64 + cb;
            float4 h = make_float4(acc[r][s][0], acc[r][s][1],
                                   acc[r][s][2], acc[r][s][3]);
            *(float4*)&H[(size_t)row * FOUT + c] = h;
            float4 bb = *(const float4*)&bias[c];
            float4 o = make_float4(bb.x + sl * h.x, bb.y + sl * h.y,
                                   bb.z + sl * h.z, bb.w + sl * h.w);
            *(float4*)&OUT[(size_t)row * FOUT + c] = o;
        }
    }
}

// ---------------------------------------------------------------------------
// Edge aggregation: OUT[dst] += dinv[src]*dinv[dst] * H[src]
// FOUT/4 threads per edge, float4 gather + red.global.add.v4.f32 scatter.
// ---------------------------------------------------------------------------
template <int FOUT>
__global__ void k_agg(const float* __restrict__ H, float* __restrict__ OUT,
                      long long total)
{
    constexpr int TPE = FOUT / 4;  // threads per edge (32 or 16)
    long long gt = (long long)blockIdx.x * blockDim.x + threadIdx.x;
    if (gt >= total) return;
    int eidx = (int)(gt / TPE);
    int l    = (int)(gt % TPE);
    int s = g_src[eidx], d = g_dst[eidx];
    float w = g_dinv[s] * g_dinv[d];
    float4 v = *(const float4*)&H[(size_t)s * FOUT + l * 4];
    float* p = &OUT[(size_t)d * FOUT + l * 4];
    asm volatile("red.global.add.v4.f32 [%0], {%1,%2,%3,%4};"
                 :: "l"(p), "f"(w * v.x), "f"(w * v.y),
                    "f"(w * v.z), "f"(w * v.w)
                 : "memory");
}

// Duplicate mu into logstd half of the output
__global__ void k_dup(float4* __restrict__ out, int m4) {
    int i = blockIdx.x * blockDim.x + threadIdx.x;
    if (i < m4) out[m4 + i] = out[i];
}

// ---------------------------------------------------------------------------
extern "C" void kernel_launch(void* const* d_in, const int* in_sizes, int n_in,
                              void* d_out, int out_size)
{
    const float* x  = (const float*)d_in[0];
    const float* W1 = (const float*)d_in[1];
    const float* b1 = (const float*)d_in[2];
    const float* W2 = (const float*)d_in[3];
    const float* b2 = (const float*)d_in[4];
    const float* W3 = (const float*)d_in[5];
    const float* b3 = (const float*)d_in[6];
    const void*  ei = d_in[7];

    int n = in_sizes[0] / DIN;
    int e = in_sizes[7] / 2;
    float* out = (float*)d_out;

    float *bufA, *bufB;
    cudaGetSymbolAddress((void**)&bufA, g_bufA);
    cudaGetSymbolAddress((void**)&bufB, g_bufB);

    const int SMEM128 = (DIN * 128 + 64 * DIN) * 4;   // 96 KB
    const int SMEM64  = (DIN * 64  + 64 * DIN) * 4;   // 64 KB
    cudaFuncSetAttribute(k_gemm<128, false>,
                         cudaFuncAttributeMaxDynamicSharedMemorySize, SMEM128);
    cudaFuncSetAttribute(k_gemm<128, true>,
                         cudaFuncAttributeMaxDynamicSharedMemorySize, SMEM128);
    cudaFuncSetAttribute(k_gemm<64, true>,
                         cudaFuncAttributeMaxDynamicSharedMemorySize, SMEM64);

    // --- edge index conversion (handles int32 or int64 source data) ---
    int cnt = 2 * e;  // elements under the int64 interpretation would be 'e',
                      // but probing all 2e int64-words is only valid if the
                      // buffer really holds 2e int64s; probe min coverage:
    // Probe e int64 words: for int64 data these are the e src values (valid);
    // for int32 data these fuse (src[2i],src[2i+1]) pairs -> out of range.
    k_probe_init<<<1, 1>>>();
    k_probe<<<(e + 255) / 256, 256>>>((const long long*)ei, e, n);
    k_convert<<<(e + 255) / 256, 256>>>(ei, e);

    int nb = (n + 255) / 256;
    k_init_deg<<<nb, 256>>>(n);
    k_count_deg<<<(e + 255) / 256, 256>>>(e);
    k_rsqrt_deg<<<nb, 256>>>(n);

    int gb = (n + 63) / 64;
    long long tot128 = (long long)e * 32;
    int ab128 = (int)((tot128 + 255) / 256);
    long long tot64 = (long long)e * 16;
    int ab64 = (int)((tot64 + 255) / 256);

    // Layer 1: H=x@W1^T -> bufA; OUT init -> bufB; aggregate into bufB
    k_gemm<128, false><<<gb, 256, SMEM128>>>(x, W1, b1, bufA, bufB, n);
    k_agg<128><<<ab128, 256>>>(bufA, bufB, tot128);

    // Layer 2: in-place on bufB (each block reads only its own rows before
    // overwriting them); H -> bufA; aggregate into bufB
    k_gemm<128, true><<<gb, 256, SMEM128>>>(bufB, W2, b2, bufA, bufB, n);
    k_agg<128><<<ab128, 256>>>(bufA, bufB, tot128);

    // Layer 3: FOUT=64; OUT init directly into d_out (mu); aggregate there
    k_gemm<64, true><<<gb, 256, SMEM64>>>(bufB, W3, b3, bufA, out, n);
    k_agg<64><<<ab64, 256>>>(bufA, out, tot64);

    // logstd = mu
    int m4 = (n * 64) / 4;
    k_dup<<<(m4 + 255) / 256, 256>>>((float4*)out, m4);
}

// round 4
// speedup vs baseline: 1.5132x; 1.5132x over previous
#include <cuda_runtime.h>

#define MAXN 100000
#define MAXE 1600000
#define DIN  128

// Scratch (allocation-free rule: __device__ globals)
__device__ float g_dinv[MAXN];
__device__ int   g_deg[MAXN];
__device__ int   g_rowptr[MAXN];
__device__ int   g_cursor[MAXN];
__device__ int   g_csrc[MAXE];
__device__ int   g_src[MAXE];
__device__ int   g_dst[MAXE];
__device__ int   g_bsum[128];
__device__ int   g_boff[128];
__device__ int   g_is32;
__device__ float g_bufA[(size_t)MAXN * 128];
__device__ float g_bufB[(size_t)MAXN * 128];

// ---------------------------------------------------------------------------
// Edge index dtype probe + conversion (handles int32 or int64 edge_index)
// ---------------------------------------------------------------------------
__global__ void k_probe_init() { g_is32 = 0; }

__global__ void k_probe(const long long* __restrict__ raw, int cnt, int n) {
    int i = blockIdx.x * blockDim.x + threadIdx.x;
    if (i < cnt) {
        long long v = raw[i];
        if (v < 0 || v >= (long long)n) g_is32 = 1;
    }
}

__global__ void k_convert(const void* __restrict__ raw, int e) {
    int i = blockIdx.x * blockDim.x + threadIdx.x;
    if (i >= e) return;
    if (g_is32) {
        const int* p = (const int*)raw;
        g_src[i] = p[i];
        g_dst[i] = p[e + i];
    } else {
        const long long* p = (const long long*)raw;
        g_src[i] = (int)p[i];
        g_dst[i] = (int)p[e + i];
    }
}

// ---------------------------------------------------------------------------
// CSR build: histogram -> exclusive scan -> fill
// ---------------------------------------------------------------------------
__global__ void k_zero_deg(int n) {
    int i = blockIdx.x * blockDim.x + threadIdx.x;
    if (i < n) g_deg[i] = 0;
}

__global__ void k_hist(int e) {
    int i = blockIdx.x * blockDim.x + threadIdx.x;
    if (i < e) atomicAdd(&g_deg[g_dst[i]], 1);
}

__global__ void k_scan1(int n) {   // block=1024, per-block exclusive scan
    __shared__ int sm[1024];
    int i = blockIdx.x * 1024 + threadIdx.x;
    int v = (i < n) ? g_deg[i] : 0;
    sm[threadIdx.x] = v;
    __syncthreads();
#pragma unroll
    for (int off = 1; off < 1024; off <<= 1) {
        int t = (threadIdx.x >= off) ? sm[threadIdx.x - off] : 0;
        __syncthreads();
        sm[threadIdx.x] += t;
        __syncthreads();
    }
    if (i < n) g_rowptr[i] = sm[threadIdx.x] - v;
    if (threadIdx.x == 1023) g_bsum[blockIdx.x] = sm[1023];
}

__global__ void k_scan2(int nb) {  // 1 block of 128, nb<=128
    __shared__ int sm[128];
    int v = (threadIdx.x < nb) ? g_bsum[threadIdx.x] : 0;
    sm[threadIdx.x] = v;
    __syncthreads();
#pragma unroll
    for (int off = 1; off < 128; off <<= 1) {
        int t = (threadIdx.x >= off) ? sm[threadIdx.x - off] : 0;
        __syncthreads();
        sm[threadIdx.x] += t;
        __syncthreads();
    }
    if (threadIdx.x < nb) g_boff[threadIdx.x] = sm[threadIdx.x] - v;
}

__global__ void k_scan3(int n) {
    int i = blockIdx.x * blockDim.x + threadIdx.x;
    if (i < n) {
        int r = g_rowptr[i] + g_boff[i >> 10];
        g_rowptr[i] = r;
        g_cursor[i] = r;
    }
}

__global__ void k_fill(int e) {
    int i = blockIdx.x * blockDim.x + threadIdx.x;
    if (i >= e) return;
    int d = g_dst[i];
    int pos = atomicAdd(&g_cursor[d], 1);
    g_csrc[pos] = g_src[i];
}

__global__ void k_rsqrt_deg(int n) {
    int i = blockIdx.x * blockDim.x + threadIdx.x;
    if (i < n) g_dinv[i] = rsqrtf((float)g_deg[i] + 1.0f);  // +1 self loop
}

// ---------------------------------------------------------------------------
// GEMM: H = act(X) @ W^T   (X:[n,128], W:[FOUT,128])
// ---------------------------------------------------------------------------
template <int FOUT, bool RELU>
__global__ void __launch_bounds__(256, 2) k_gemm(
    const float* __restrict__ X, const float* __restrict__ W,
    float* __restrict__ H, int n)
{
    extern __shared__ float sm[];
    float* Ws = sm;               // [DIN][FOUT]  (W transposed)
    float* Xs = sm + DIN * FOUT;  // [64][DIN]

    const int tid  = threadIdx.x;
    const int row0 = blockIdx.x * 64;

    for (int idx = tid; idx < FOUT * DIN / 4; idx += 256) {
        float4 w = ((const float4*)W)[idx];
        int c = (idx * 4) / DIN, k = (idx * 4) % DIN;
        Ws[(k + 0) * FOUT + c] = w.x;
        Ws[(k + 1) * FOUT + c] = w.y;
        Ws[(k + 2) * FOUT + c] = w.z;
        Ws[(k + 3) * FOUT + c] = w.w;
    }
    for (int idx = tid; idx < 64 * DIN / 4; idx += 256) {
        int r = (idx * 4) / DIN, k = (idx * 4) % DIN;
        int row = row0 + r;
        float4 v = make_float4(0.f, 0.f, 0.f, 0.f);
        if (row < n) {
            v = *(const float4*)&X[(size_t)row * DIN + k];
            if (RELU) {
                v.x = fmaxf(v.x, 0.f); v.y = fmaxf(v.y, 0.f);
                v.z = fmaxf(v.z, 0.f); v.w = fmaxf(v.w, 0.f);
            }
        }
        *(float4*)&Xs[r * DIN + k] = v;
    }
    __syncthreads();

    constexpr int NSEG = FOUT / 64;
    const int tx = tid & 15, ty = tid >> 4;
    const int cb = tx * 4;

    float acc[4][NSEG][4];
#pragma unroll
    for (int r = 0; r < 4; r++)
#pragma unroll
        for (int s = 0; s < NSEG; s++)
#pragma unroll
            for (int j = 0; j < 4; j++) acc[r][s][j] = 0.f;

#pragma unroll 2
    for (int k = 0; k < DIN; k += 4) {
        float4 a[4];
#pragma unroll
        for (int r = 0; r < 4; r++)
            a[r] = *(const float4*)&Xs[(ty * 4 + r) * DIN + k];
#pragma unroll
        for (int kk = 0; kk < 4; kk++) {
#pragma unroll
            for (int s = 0; s < NSEG; s++) {
                float4 b = *(const float4*)&Ws[(k + kk) * FOUT + s * 64 + cb];
#pragma unroll
                for (int r = 0; r < 4; r++) {
                    float av = ((const float*)&a[r])[kk];
                    acc[r][s][0] += av * b.x;
                    acc[r][s][1] += av * b.y;
                    acc[r][s][2] += av * b.z;
                    acc[r][s][3] += av * b.w;
                }
            }
        }
    }

#pragma unroll
    for (int r = 0; r < 4; r++) {
        int row = row0 + ty * 4 + r;
        if (row >= n) continue;
#pragma unroll
        for (int s = 0; s < NSEG; s++) {
            int c = s * 64 + cb;
            float4 h = make_float4(acc[r][s][0], acc[r][s][1],
                                   acc[r][s][2], acc[r][s][3]);
            *(float4*)&H[(size_t)row * FOUT + c] = h;
        }
    }
}

// ---------------------------------------------------------------------------
// CSR aggregation: one warp per dst node, register accumulation, no atomics.
// OUT[d] = bias + dinv[d] * ( dinv[d]*H[d] + sum_{s in in(d)} dinv[s]*H[s] )
// ---------------------------------------------------------------------------
__global__ void __launch_bounds__(256) k_agg128(
    const float* __restrict__ H, const float* __restrict__ bias,
    float* __restrict__ OUT, int n)
{
    int node = blockIdx.x * 8 + (threadIdx.x >> 5);
    if (node >= n) return;
    int lane = threadIdx.x & 31;

    int beg = g_rowptr[node];
    int dg  = g_deg[node];
    int end = beg + dg;

    float4 acc = make_float4(0.f, 0.f, 0.f, 0.f);
    int j = beg;
    for (; j + 4 <= end; j += 4) {
        int s0 = g_csrc[j], s1 = g_csrc[j + 1];
        int s2 = g_csrc[j + 2], s3 = g_csrc[j + 3];
        float w0 = g_dinv[s0], w1 = g_dinv[s1];
        float w2 = g_dinv[s2], w3 = g_dinv[s3];
        float4 v0 = *(const float4*)&H[(size_t)s0 * 128 + lane * 4];
        float4 v1 = *(const float4*)&H[(size_t)s1 * 128 + lane * 4];
        float4 v2 = *(const float4*)&H[(size_t)s2 * 128 + lane * 4];
        float4 v3 = *(const float4*)&H[(size_t)s3 * 128 + lane * 4];
        acc.x += w0 * v0.x + w1 * v1.x + w2 * v2.x + w3 * v3.x;
        acc.y += w0 * v0.y + w1 * v1.y + w2 * v2.y + w3 * v3.y;
        acc.z += w0 * v0.z + w1 * v1.z + w2 * v2.z + w3 * v3.z;
        acc.w += w0 * v0.w + w1 * v1.w + w2 * v2.w + w3 * v3.w;
    }
    for (; j < end; j++) {
        int s = g_csrc[j];
        float w = g_dinv[s];
        float4 v = *(const float4*)&H[(size_t)s * 128 + lane * 4];
        acc.x += w * v.x; acc.y += w * v.y;
        acc.z += w * v.z; acc.w += w * v.w;
    }

    float di = g_dinv[node];
    float4 hs = *(const float4*)&H[(size_t)node * 128 + lane * 4];
    float4 bb = *(const float4*)&bias[lane * 4];
    float4 o;
    o.x = bb.x + di * (acc.x + di * hs.x);
    o.y = bb.y + di * (acc.y + di * hs.y);
    o.z = bb.z + di * (acc.z + di * hs.z);
    o.w = bb.w + di * (acc.w + di * hs.w);
    *(float4*)&OUT[(size_t)node * 128 + lane * 4] = o;
}

// FOUT=64 variant: float2 per lane; writes mu and logstd (duplicate).
__global__ void __launch_bounds__(256) k_agg64(
    const float* __restrict__ H, const float* __restrict__ bias,
    float* __restrict__ OUT, int n)
{
    int node = blockIdx.x * 8 + (threadIdx.x >> 5);
    if (node >= n) return;
    int lane = threadIdx.x & 31;

    int beg = g_rowptr[node];
    int dg  = g_deg[node];
    int end = beg + dg;

    float2 acc = make_float2(0.f, 0.f);
    int j = beg;
    for (; j + 4 <= end; j += 4) {
        int s0 = g_csrc[j], s1 = g_csrc[j + 1];
        int s2 = g_csrc[j + 2], s3 = g_csrc[j + 3];
        float w0 = g_dinv[s0], w1 = g_dinv[s1];
        float w2 = g_dinv[s2], w3 = g_dinv[s3];
        float2 v0 = *(const float2*)&H[(size_t)s0 * 64 + lane * 2];
        float2 v1 = *(const float2*)&H[(size_t)s1 * 64 + lane * 2];
        float2 v2 = *(const float2*)&H[(size_t)s2 * 64 + lane * 2];
        float2 v3 = *(const float2*)&H[(size_t)s3 * 64 + lane * 2];
        acc.x += w0 * v0.x + w1 * v1.x + w2 * v2.x + w3 * v3.x;
        acc.y += w0 * v0.y + w1 * v1.y + w2 * v2.y + w3 * v3.y;
    }
    for (; j < end; j++) {
        int s = g_csrc[j];
        float w = g_dinv[s];
        float2 v = *(const float2*)&H[(size_t)s * 64 + lane * 2];
        acc.x += w * v.x; acc.y += w * v.y;
    }

    float di = g_dinv[node];
    float2 hs = *(const float2*)&H[(size_t)node * 64 + lane * 2];
    float2 bb = *(const float2*)&bias[lane * 2];
    float2 o;
    o.x = bb.x + di * (acc.x + di * hs.x);
    o.y = bb.y + di * (acc.y + di * hs.y);
    *(float2*)&OUT[(size_t)node * 64 + lane * 2] = o;                  // mu
    *(float2*)&OUT[(size_t)(n + node) * 64 + lane * 2] = o;            // logstd
}

// ---------------------------------------------------------------------------
extern "C" void kernel_launch(void* const* d_in, const int* in_sizes, int n_in,
                              void* d_out, int out_size)
{
    const float* x  = (const float*)d_in[0];
    const float* W1 = (const float*)d_in[1];
    const float* b1 = (const float*)d_in[2];
    const float* W2 = (const float*)d_in[3];
    const float* b2 = (const float*)d_in[4];
    const float* W3 = (const float*)d_in[5];
    const float* b3 = (const float*)d_in[6];
    const void*  ei = d_in[7];

    int n = in_sizes[0] / DIN;
    int e = in_sizes[7] / 2;
    float* out = (float*)d_out;

    float *bufA, *bufB;
    cudaGetSymbolAddress((void**)&bufA, g_bufA);
    cudaGetSymbolAddress((void**)&bufB, g_bufB);

    const int SMEM128 = (DIN * 128 + 64 * DIN) * 4;   // 96 KB
    const int SMEM64  = (DIN * 64  + 64 * DIN) * 4;   // 64 KB
    cudaFuncSetAttribute(k_gemm<128, false>,
                         cudaFuncAttributeMaxDynamicSharedMemorySize, SMEM128);
    cudaFuncSetAttribute(k_gemm<128, true>,
                         cudaFuncAttributeMaxDynamicSharedMemorySize, SMEM128);
    cudaFuncSetAttribute(k_gemm<64, true>,
                         cudaFuncAttributeMaxDynamicSharedMemorySize, SMEM64);

    int nb  = (n + 255) / 256;
    int ebk = (e + 255) / 256;
    int nsb = (n + 1023) / 1024;   // scan blocks (<=128)

    // --- edge conversion + CSR build + normalization ---
    k_probe_init<<<1, 1>>>();
    k_probe<<<ebk, 256>>>((const long long*)ei, e, n);
    k_convert<<<ebk, 256>>>(ei, e);
    k_zero_deg<<<nb, 256>>>(n);
    k_hist<<<ebk, 256>>>(e);
    k_scan1<<<nsb, 1024>>>(n);
    k_scan2<<<1, 128>>>(nsb);
    k_scan3<<<nb, 256>>>(n);
    k_fill<<<ebk, 256>>>(e);
    k_rsqrt_deg<<<nb, 256>>>(n);

    int gb = (n + 63) / 64;        // GEMM blocks
    int ag = (n + 7) / 8;          // agg blocks (8 nodes/block)

    // Layer 1
    k_gemm<128, false><<<gb, 256, SMEM128>>>(x, W1, bufA, n);
    k_agg128<<<ag, 256>>>(bufA, b1, bufB, n);
    // Layer 2
    k_gemm<128, true><<<gb, 256, SMEM128>>>(bufB, W2, bufA, n);
    k_agg128<<<ag, 256>>>(bufA, b2, bufB, n);
    // Layer 3 (FOUT=64) -> mu & logstd
    k_gemm<64, true><<<gb, 256, SMEM64>>>(bufB, W3, bufA, n);
    k_agg64<<<ag, 256>>>(bufA, b3, out, n);
}

// round 5
// speedup vs baseline: 1.5174x; 1.0028x over previous
#include <cuda_runtime.h>

#define MAXN 100000
#define MAXE 1600000
#define DIN  128

// Scratch (allocation-free rule: __device__ globals)
__device__ float g_dinv[MAXN];
__device__ int   g_deg[MAXN];
__device__ int   g_rowptr[MAXN];
__device__ int   g_cursor[MAXN];
__device__ int   g_csrc[MAXE];
__device__ int   g_src[MAXE];
__device__ int   g_dst[MAXE];
__device__ int   g_bsum[128];
__device__ int   g_boff[128];
__device__ int   g_is32;
__device__ float g_bufA[(size_t)MAXN * 128];
__device__ float g_bufB[(size_t)MAXN * 128];

// ---------------------------------------------------------------------------
// Edge index dtype probe + conversion (handles int32 or int64 edge_index)
// ---------------------------------------------------------------------------
__global__ void k_probe_init() { g_is32 = 0; }

__global__ void k_probe(const long long* __restrict__ raw, int cnt, int n) {
    int i = blockIdx.x * blockDim.x + threadIdx.x;
    if (i < cnt) {
        long long v = raw[i];
        if (v < 0 || v >= (long long)n) g_is32 = 1;
    }
}

__global__ void k_convert(const void* __restrict__ raw, int e) {
    int i = blockIdx.x * blockDim.x + threadIdx.x;
    if (i >= e) return;
    if (g_is32) {
        const int* p = (const int*)raw;
        g_src[i] = p[i];
        g_dst[i] = p[e + i];
    } else {
        const long long* p = (const long long*)raw;
        g_src[i] = (int)p[i];
        g_dst[i] = (int)p[e + i];
    }
}

// ---------------------------------------------------------------------------
// CSR build: histogram -> exclusive scan -> fill
// ---------------------------------------------------------------------------
__global__ void k_zero_deg(int n) {
    int i = blockIdx.x * blockDim.x + threadIdx.x;
    if (i < n) g_deg[i] = 0;
}

__global__ void k_hist(int e) {
    int i = blockIdx.x * blockDim.x + threadIdx.x;
    if (i < e) atomicAdd(&g_deg[g_dst[i]], 1);
}

__global__ void k_scan1(int n) {   // block=1024, per-block exclusive scan
    __shared__ int sm[1024];
    int i = blockIdx.x * 1024 + threadIdx.x;
    int v = (i < n) ? g_deg[i] : 0;
    sm[threadIdx.x] = v;
    __syncthreads();
#pragma unroll
    for (int off = 1; off < 1024; off <<= 1) {
        int t = (threadIdx.x >= off) ? sm[threadIdx.x - off] : 0;
        __syncthreads();
        sm[threadIdx.x] += t;
        __syncthreads();
    }
    if (i < n) g_rowptr[i] = sm[threadIdx.x] - v;
    if (threadIdx.x == 1023) g_bsum[blockIdx.x] = sm[1023];
}

__global__ void k_scan2(int nb) {  // 1 block of 128, nb<=128
    __shared__ int sm[128];
    int v = (threadIdx.x < nb) ? g_bsum[threadIdx.x] : 0;
    sm[threadIdx.x] = v;
    __syncthreads();
#pragma unroll
    for (int off = 1; off < 128; off <<= 1) {
        int t = (threadIdx.x >= off) ? sm[threadIdx.x - off] : 0;
        __syncthreads();
        sm[threadIdx.x] += t;
        __syncthreads();
    }
    if (threadIdx.x < nb) g_boff[threadIdx.x] = sm[threadIdx.x] - v;
}

__global__ void k_scan3(int n) {
    int i = blockIdx.x * blockDim.x + threadIdx.x;
    if (i < n) {
        int r = g_rowptr[i] + g_boff[i >> 10];
        g_rowptr[i] = r;
        g_cursor[i] = r;
    }
}

__global__ void k_fill(int e) {
    int i = blockIdx.x * blockDim.x + threadIdx.x;
    if (i >= e) return;
    int d = g_dst[i];
    int pos = atomicAdd(&g_cursor[d], 1);
    g_csrc[pos] = g_src[i];
}

__global__ void k_rsqrt_deg(int n) {
    int i = blockIdx.x * blockDim.x + threadIdx.x;
    if (i < n) g_dinv[i] = rsqrtf((float)g_deg[i] + 1.0f);  // +1 self loop
}

// ---------------------------------------------------------------------------
// GEMM: H = act(X) @ W^T   (X:[n,128], W:[FOUT,128])
// ---------------------------------------------------------------------------
template <int FOUT, bool RELU>
__global__ void __launch_bounds__(256, 2) k_gemm(
    const float* __restrict__ X, const float* __restrict__ W,
    float* __restrict__ H, int n)
{
    extern __shared__ float sm[];
    float* Ws = sm;               // [DIN][FOUT]  (W transposed)
    float* Xs = sm + DIN * FOUT;  // [64][DIN]

    const int tid  = threadIdx.x;
    const int row0 = blockIdx.x * 64;

    for (int idx = tid; idx < FOUT * DIN / 4; idx += 256) {
        float4 w = ((const float4*)W)[idx];
        int c = (idx * 4) / DIN, k = (idx * 4) % DIN;
        Ws[(k + 0) * FOUT + c] = w.x;
        Ws[(k + 1) * FOUT + c] = w.y;
        Ws[(k + 2) * FOUT + c] = w.z;
        Ws[(k + 3) * FOUT + c] = w.w;
    }
    for (int idx = tid; idx < 64 * DIN / 4; idx += 256) {
        int r = (idx * 4) / DIN, k = (idx * 4) % DIN;
        int row = row0 + r;
        float4 v = make_float4(0.f, 0.f, 0.f, 0.f);
        if (row < n) {
            v = *(const float4*)&X[(size_t)row * DIN + k];
            if (RELU) {
                v.x = fmaxf(v.x, 0.f); v.y = fmaxf(v.y, 0.f);
                v.z = fmaxf(v.z, 0.f); v.w = fmaxf(v.w, 0.f);
            }
        }
        *(float4*)&Xs[r * DIN + k] = v;
    }
    __syncthreads();

    constexpr int NSEG = FOUT / 64;
    const int tx = tid & 15, ty = tid >> 4;
    const int cb = tx * 4;

    float acc[4][NSEG][4];
#pragma unroll
    for (int r = 0; r < 4; r++)
#pragma unroll
        for (int s = 0; s < NSEG; s++)
#pragma unroll
            for (int j = 0; j < 4; j++) acc[r][s][j] = 0.f;

#pragma unroll 2
    for (int k = 0; k < DIN; k += 4) {
        float4 a[4];
#pragma unroll
        for (int r = 0; r < 4; r++)
            a[r] = *(const float4*)&Xs[(ty * 4 + r) * DIN + k];
#pragma unroll
        for (int kk = 0; kk < 4; kk++) {
#pragma unroll
            for (int s = 0; s < NSEG; s++) {
                float4 b = *(const float4*)&Ws[(k + kk) * FOUT + s * 64 + cb];
#pragma unroll
                for (int r = 0; r < 4; r++) {
                    float av = ((const float*)&a[r])[kk];
                    acc[r][s][0] += av * b.x;
                    acc[r][s][1] += av * b.y;
                    acc[r][s][2] += av * b.z;
                    acc[r][s][3] += av * b.w;
                }
            }
        }
    }

#pragma unroll
    for (int r = 0; r < 4; r++) {
        int row = row0 + ty * 4 + r;
        if (row >= n) continue;
#pragma unroll
        for (int s = 0; s < NSEG; s++) {
            int c = s * 64 + cb;
            float4 h = make_float4(acc[r][s][0], acc[r][s][1],
                                   acc[r][s][2], acc[r][s][3]);
            *(float4*)&H[(size_t)row * FOUT + c] = h;
        }
    }
}

// ---------------------------------------------------------------------------
// CSR aggregation: one warp per dst node, register accumulation, no atomics.
// OUT[d] = bias + dinv[d] * ( dinv[d]*H[d] + sum_{s in in(d)} dinv[s]*H[s] )
// ---------------------------------------------------------------------------
__global__ void __launch_bounds__(256) k_agg128(
    const float* __restrict__ H, const float* __restrict__ bias,
    float* __restrict__ OUT, int n)
{
    int node = blockIdx.x * 8 + (threadIdx.x >> 5);
    if (node >= n) return;
    int lane = threadIdx.x & 31;

    int beg = g_rowptr[node];
    int dg  = g_deg[node];
    int end = beg + dg;

    float4 acc = make_float4(0.f, 0.f, 0.f, 0.f);
    int j = beg;
    for (; j + 4 <= end; j += 4) {
        int s0 = g_csrc[j], s1 = g_csrc[j + 1];
        int s2 = g_csrc[j + 2], s3 = g_csrc[j + 3];
        float w0 = g_dinv[s0], w1 = g_dinv[s1];
        float w2 = g_dinv[s2], w3 = g_dinv[s3];
        float4 v0 = *(const float4*)&H[(size_t)s0 * 128 + lane * 4];
        float4 v1 = *(const float4*)&H[(size_t)s1 * 128 + lane * 4];
        float4 v2 = *(const float4*)&H[(size_t)s2 * 128 + lane * 4];
        float4 v3 = *(const float4*)&H[(size_t)s3 * 128 + lane * 4];
        acc.x += w0 * v0.x + w1 * v1.x + w2 * v2.x + w3 * v3.x;
        acc.y += w0 * v0.y + w1 * v1.y + w2 * v2.y + w3 * v3.y;
        acc.z += w0 * v0.z + w1 * v1.z + w2 * v2.z + w3 * v3.z;
        acc.w += w0 * v0.w + w1 * v1.w + w2 * v2.w + w3 * v3.w;
    }
    for (; j < end; j++) {
        int s = g_csrc[j];
        float w = g_dinv[s];
        float4 v = *(const float4*)&H[(size_t)s * 128 + lane * 4];
        acc.x += w * v.x; acc.y += w * v.y;
        acc.z += w * v.z; acc.w += w * v.w;
    }

    float di = g_dinv[node];
    float4 hs = *(const float4*)&H[(size_t)node * 128 + lane * 4];
    float4 bb = *(const float4*)&bias[lane * 4];
    float4 o;
    o.x = bb.x + di * (acc.x + di * hs.x);
    o.y = bb.y + di * (acc.y + di * hs.y);
    o.z = bb.z + di * (acc.z + di * hs.z);
    o.w = bb.w + di * (acc.w + di * hs.w);
    *(float4*)&OUT[(size_t)node * 128 + lane * 4] = o;
}

// FOUT=64 variant: float2 per lane; writes mu and logstd (duplicate).
__global__ void __launch_bounds__(256) k_agg64(
    const float* __restrict__ H, const float* __restrict__ bias,
    float* __restrict__ OUT, int n)
{
    int node = blockIdx.x * 8 + (threadIdx.x >> 5);
    if (node >= n) return;
    int lane = threadIdx.x & 31;

    int beg = g_rowptr[node];
    int dg  = g_deg[node];
    int end = beg + dg;

    float2 acc = make_float2(0.f, 0.f);
    int j = beg;
    for (; j + 4 <= end; j += 4) {
        int s0 = g_csrc[j], s1 = g_csrc[j + 1];
        int s2 = g_csrc[j + 2], s3 = g_csrc[j + 3];
        float w0 = g_dinv[s0], w1 = g_dinv[s1];
        float w2 = g_dinv[s2], w3 = g_dinv[s3];
        float2 v0 = *(const float2*)&H[(size_t)s0 * 64 + lane * 2];
        float2 v1 = *(const float2*)&H[(size_t)s1 * 64 + lane * 2];
        float2 v2 = *(const float2*)&H[(size_t)s2 * 64 + lane * 2];
        float2 v3 = *(const float2*)&H[(size_t)s3 * 64 + lane * 2];
        acc.x += w0 * v0.x + w1 * v1.x + w2 * v2.x + w3 * v3.x;
        acc.y += w0 * v0.y + w1 * v1.y + w2 * v2.y + w3 * v3.y;
    }
    for (; j < end; j++) {
        int s = g_csrc[j];
        float w = g_dinv[s];
        float2 v = *(const float2*)&H[(size_t)s * 64 + lane * 2];
        acc.x += w * v.x; acc.y += w * v.y;
    }

    float di = g_dinv[node];
    float2 hs = *(const float2*)&H[(size_t)node * 64 + lane * 2];
    float2 bb = *(const float2*)&bias[lane * 2];
    float2 o;
    o.x = bb.x + di * (acc.x + di * hs.x);
    o.y = bb.y + di * (acc.y + di * hs.y);
    *(float2*)&OUT[(size_t)node * 64 + lane * 2] = o;                  // mu
    *(float2*)&OUT[(size_t)(n + node) * 64 + lane * 2] = o;            // logstd
}

// ---------------------------------------------------------------------------
extern "C" void kernel_launch(void* const* d_in, const int* in_sizes, int n_in,
                              void* d_out, int out_size)
{
    const float* x  = (const float*)d_in[0];
    const float* W1 = (const float*)d_in[1];
    const float* b1 = (const float*)d_in[2];
    const float* W2 = (const float*)d_in[3];
    const float* b2 = (const float*)d_in[4];
    const float* W3 = (const float*)d_in[5];
    const float* b3 = (const float*)d_in[6];
    const void*  ei = d_in[7];

    int n = in_sizes[0] / DIN;
    int e = in_sizes[7] / 2;
    float* out = (float*)d_out;

    float *bufA, *bufB;
    cudaGetSymbolAddress((void**)&bufA, g_bufA);
    cudaGetSymbolAddress((void**)&bufB, g_bufB);

    const int SMEM128 = (DIN * 128 + 64 * DIN) * 4;   // 96 KB
    const int SMEM64  = (DIN * 64  + 64 * DIN) * 4;   // 64 KB
    cudaFuncSetAttribute(k_gemm<128, false>,
                         cudaFuncAttributeMaxDynamicSharedMemorySize, SMEM128);
    cudaFuncSetAttribute(k_gemm<128, true>,
                         cudaFuncAttributeMaxDynamicSharedMemorySize, SMEM128);
    cudaFuncSetAttribute(k_gemm<64, true>,
                         cudaFuncAttributeMaxDynamicSharedMemorySize, SMEM64);

    int nb  = (n + 255) / 256;
    int ebk = (e + 255) / 256;
    int nsb = (n + 1023) / 1024;   // scan blocks (<=128)

    // --- edge conversion + CSR build + normalization ---
    k_probe_init<<<1, 1>>>();
    k_probe<<<ebk, 256>>>((const long long*)ei, e, n);
    k_convert<<<ebk, 256>>>(ei, e);
    k_zero_deg<<<nb, 256>>>(n);
    k_hist<<<ebk, 256>>>(e);
    k_scan1<<<nsb, 1024>>>(n);
    k_scan2<<<1, 128>>>(nsb);
    k_scan3<<<nb, 256>>>(n);
    k_fill<<<ebk, 256>>>(e);
    k_rsqrt_deg<<<nb, 256>>>(n);

    int gb = (n + 63) / 64;        // GEMM blocks
    int ag = (n + 7) / 8;          // agg blocks (8 nodes/block)

    // Layer 1
    k_gemm<128, false><<<gb, 256, SMEM128>>>(x, W1, bufA, n);
    k_agg128<<<ag, 256>>>(bufA, b1, bufB, n);
    // Layer 2
    k_gemm<128, true><<<gb, 256, SMEM128>>>(bufB, W2, bufA, n);
    k_agg128<<<ag, 256>>>(bufA, b2, bufB, n);
    // Layer 3 (FOUT=64) -> mu & logstd
    k_gemm<64, true><<<gb, 256, SMEM64>>>(bufB, W3, bufA, n);
    k_agg64<<<ag, 256>>>(bufA, b3, out, n);
}

// round 8
// speedup vs baseline: 2.1409x; 1.4109x over previous
#include <cuda_runtime.h>
#include <cuda_bf16.h>
#include <cstdint>

#define MAXN 100000
#define MAXE 1600000
#define DIN  128

// ---------------------------------------------------------------------------
// Scratch (allocation-free rule: __device__ globals)
// ---------------------------------------------------------------------------
__device__ float g_dinv[MAXN];
__device__ int   g_deg[MAXN];
__device__ int   g_rowptr[MAXN];
__device__ int   g_cursor[MAXN];
__device__ int   g_csrc[MAXE];
__device__ int   g_src[MAXE];
__device__ int   g_dst[MAXE];
__device__ int   g_bsum[128];
__device__ int   g_boff[128];
__device__ int   g_is32;
__device__ float g_bufA[(size_t)MAXN * 128];
__device__ float g_bufB[(size_t)MAXN * 128];
// Pre-split weights: W1(128x128), W2(128x128), W3(64x128) -> 320*128 elems
__device__ __nv_bfloat16 g_wh[320 * 128];
__device__ __nv_bfloat16 g_wl[320 * 128];

// ---------------------------------------------------------------------------
// Edge index dtype probe + conversion (+ fused degree histogram)
// ---------------------------------------------------------------------------
__global__ void k_probe_init() { g_is32 = 0; }

__global__ void k_probe(const long long* __restrict__ raw, int cnt, int n) {
    int i = blockIdx.x * blockDim.x + threadIdx.x;
    if (i < cnt) {
        long long v = raw[i];
        if (v < 0 || v >= (long long)n) g_is32 = 1;
    }
}

__global__ void k_zero_deg(int n) {
    int i = blockIdx.x * blockDim.x + threadIdx.x;
    if (i < n) g_deg[i] = 0;
}

__global__ void k_convert_hist(const void* __restrict__ raw, int e) {
    int i = blockIdx.x * blockDim.x + threadIdx.x;
    if (i >= e) return;
    int s, d;
    if (g_is32) {
        const int* p = (const int*)raw;
        s = p[i]; d = p[e + i];
    } else {
        const long long* p = (const long long*)raw;
        s = (int)p[i]; d = (int)p[e + i];
    }
    g_src[i] = s; g_dst[i] = d;
    atomicAdd(&g_deg[d], 1);
}

// ---------------------------------------------------------------------------
// CSR build: exclusive scan + fill
// ---------------------------------------------------------------------------
__global__ void k_scan1(int n) {
    __shared__ int sm[1024];
    int i = blockIdx.x * 1024 + threadIdx.x;
    int v = (i < n) ? g_deg[i] : 0;
    sm[threadIdx.x] = v;
    __syncthreads();
#pragma unroll
    for (int off = 1; off < 1024; off <<= 1) {
        int t = (threadIdx.x >= off) ? sm[threadIdx.x - off] : 0;
        __syncthreads();
        sm[threadIdx.x] += t;
        __syncthreads();
    }
    if (i < n) g_rowptr[i] = sm[threadIdx.x] - v;
    if (threadIdx.x == 1023) g_bsum[blockIdx.x] = sm[1023];
}

__global__ void k_scan2(int nb) {
    __shared__ int sm[128];
    int v = (threadIdx.x < nb) ? g_bsum[threadIdx.x] : 0;
    sm[threadIdx.x] = v;
    __syncthreads();
#pragma unroll
    for (int off = 1; off < 128; off <<= 1) {
        int t = (threadIdx.x >= off) ? sm[threadIdx.x - off] : 0;
        __syncthreads();
        sm[threadIdx.x] += t;
        __syncthreads();
    }
    if (threadIdx.x < nb) g_boff[threadIdx.x] = sm[threadIdx.x] - v;
}

__global__ void k_scan3(int n) {   // + fused rsqrt normalization
    int i = blockIdx.x * blockDim.x + threadIdx.x;
    if (i < n) {
        int r = g_rowptr[i] + g_boff[i >> 10];
        g_rowptr[i] = r;
        g_cursor[i] = r;
        g_dinv[i] = rsqrtf((float)g_deg[i] + 1.0f);
    }
}

__global__ void k_fill(int e) {
    int i = blockIdx.x * blockDim.x + threadIdx.x;
    if (i >= e) return;
    int d = g_dst[i];
    int pos = atomicAdd(&g_cursor[d], 1);
    g_csrc[pos] = g_src[i];
}

// ---------------------------------------------------------------------------
// Weight split: W (fp32) -> hi/lo bf16
// ---------------------------------------------------------------------------
__global__ void k_prep_w(const float* __restrict__ W1, const float* __restrict__ W2,
                         const float* __restrict__ W3) {
    int i = blockIdx.x * blockDim.x + threadIdx.x;
    if (i >= 320 * 128) return;
    float v;
    if (i < 16384)       v = W1[i];
    else if (i < 32768)  v = W2[i - 16384];
    else                 v = W3[i - 32768];
    __nv_bfloat16 h = __float2bfloat16_rn(v);
    g_wh[i] = h;
    g_wl[i] = __float2bfloat16_rn(v - __bfloat162float(h));
}

// ---------------------------------------------------------------------------
// mma.sync bf16 split GEMM: H[128 x FOUT tile] = act(X) @ W^T
// D = Ahi*Bhi + Alo*Bhi + Ahi*Blo  (fp32 accumulate, lo*lo dropped ~2^-18)
// ---------------------------------------------------------------------------
__device__ __forceinline__ void mma16816(float* c, const uint32_t* a,
                                         uint32_t b0, uint32_t b1) {
    asm volatile(
        "mma.sync.aligned.m16n8k16.row.col.f32.bf16.bf16.f32 "
        "{%0,%1,%2,%3}, {%4,%5,%6,%7}, {%8,%9}, {%0,%1,%2,%3};"
        : "+f"(c[0]), "+f"(c[1]), "+f"(c[2]), "+f"(c[3])
        : "r"(a[0]), "r"(a[1]), "r"(a[2]), "r"(a[3]), "r"(b0), "r"(b1));
}

template <int FOUT, bool RELU>
__global__ void __launch_bounds__(256, 1) k_mma(
    const float* __restrict__ X, const __nv_bfloat16* __restrict__ Wh,
    const __nv_bfloat16* __restrict__ Wl, float* __restrict__ H, int n)
{
    constexpr int RS = 136;     // smem row stride in bf16 (272B: conflict-free)
    constexpr int NT = FOUT / 8;
    extern __shared__ __nv_bfloat16 sm[];
    __nv_bfloat16* Ah = sm;                       // [8][16][RS]
    __nv_bfloat16* Al = Ah + 8 * 16 * RS;
    __nv_bfloat16* Bh = Al + 8 * 16 * RS;         // [FOUT][RS]
    __nv_bfloat16* Bl = Bh + FOUT * RS;

    const int tid = threadIdx.x, wid = tid >> 5, lane = tid & 31;
    const int row0 = blockIdx.x * 128;

    // ---- stage pre-split weights into SMEM ----
    for (int idx = tid; idx < FOUT * 32; idx += 256) {
        int r = idx >> 5, c4 = idx & 31;
        *(uint2*)&Bh[r * RS + c4 * 4] = *(const uint2*)&Wh[r * 128 + c4 * 4];
        *(uint2*)&Bl[r * RS + c4 * 4] = *(const uint2*)&Wl[r * 128 + c4 * 4];
    }

    // ---- each warp converts its 16 fp32 rows -> hi/lo bf16 (ReLU fused) ----
    __nv_bfloat16* Awh = Ah + wid * 16 * RS;
    __nv_bfloat16* Awl = Al + wid * 16 * RS;
    for (int idx = lane; idx < 16 * 32; idx += 32) {
        int r = idx >> 5, c4 = idx & 31;
        int grow = row0 + wid * 16 + r;
        float4 v = make_float4(0.f, 0.f, 0.f, 0.f);
        if (grow < n) {
            v = *(const float4*)&X[(size_t)grow * 128 + c4 * 4];
            if (RELU) {
                v.x = fmaxf(v.x, 0.f); v.y = fmaxf(v.y, 0.f);
                v.z = fmaxf(v.z, 0.f); v.w = fmaxf(v.w, 0.f);
            }
        }
        __nv_bfloat162 h01 = __floats2bfloat162_rn(v.x, v.y);
        __nv_bfloat162 h23 = __floats2bfloat162_rn(v.z, v.w);
        float2 f01 = __bfloat1622float2(h01);
        float2 f23 = __bfloat1622float2(h23);
        __nv_bfloat162 l01 = __floats2bfloat162_rn(v.x - f01.x, v.y - f01.y);
        __nv_bfloat162 l23 = __floats2bfloat162_rn(v.z - f23.x, v.w - f23.y);
        *(uint2*)&Awh[r * RS + c4 * 4] =
            make_uint2(*(uint32_t*)&h01, *(uint32_t*)&h23);
        *(uint2*)&Awl[r * RS + c4 * 4] =
            make_uint2(*(uint32_t*)&l01, *(uint32_t*)&l23);
    }
    __syncthreads();

    float acc[NT][4];
#pragma unroll
    for (int t = 0; t < NT; t++)
#pragma unroll
        for (int j = 0; j < 4; j++) acc[t][j] = 0.f;

    const int qr = lane >> 2;           // quad row
    const int qc = (lane & 3) * 2;      // quad col (k or n offset)

#pragma unroll
    for (int ks = 0; ks < 8; ks++) {
        const int kb = ks * 16;
        uint32_t ah[4], al[4];
        ah[0] = *(const uint32_t*)&Awh[(qr)     * RS + kb + qc];
        ah[1] = *(const uint32_t*)&Awh[(qr + 8) * RS + kb + qc];
        ah[2] = *(const uint32_t*)&Awh[(qr)     * RS + kb + 8 + qc];
        ah[3] = *(const uint32_t*)&Awh[(qr + 8) * RS + kb + 8 + qc];
        al[0] = *(const uint32_t*)&Awl[(qr)     * RS + kb + qc];
        al[1] = *(const uint32_t*)&Awl[(qr + 8) * RS + kb + qc];
        al[2] = *(const uint32_t*)&Awl[(qr)     * RS + kb + 8 + qc];
        al[3] = *(const uint32_t*)&Awl[(qr + 8) * RS + kb + 8 + qc];
#pragma unroll
        for (int nt = 0; nt < NT; nt++) {
            int nr = nt * 8 + qr;
            uint32_t bh0 = *(const uint32_t*)&Bh[nr * RS + kb + qc];
            uint32_t bh1 = *(const uint32_t*)&Bh[nr * RS + kb + 8 + qc];
            mma16816(acc[nt], ah, bh0, bh1);
            mma16816(acc[nt], al, bh0, bh1);
            uint32_t bl0 = *(const uint32_t*)&Bl[nr * RS + kb + qc];
            uint32_t bl1 = *(const uint32_t*)&Bl[nr * RS + kb + 8 + qc];
            mma16816(acc[nt], ah, bl0, bl1);
        }
    }

    // ---- epilogue ----
    const int r0 = row0 + wid * 16 + qr;
    const int r1 = r0 + 8;
#pragma unroll
    for (int nt = 0; nt < NT; nt++) {
        int col = nt * 8 + qc;
        if (r0 < n)
            *(float2*)&H[(size_t)r0 * FOUT + col] = make_float2(acc[nt][0], acc[nt][1]);
        if (r1 < n)
            *(float2*)&H[(size_t)r1 * FOUT + col] = make_float2(acc[nt][2], acc[nt][3]);
    }
}

// ---------------------------------------------------------------------------
// CSR aggregation: one warp per dst node, register accumulation, no atomics.
// OUT[d] = bias + dinv[d] * ( dinv[d]*H[d] + sum_{s in in(d)} dinv[s]*H[s] )
// ---------------------------------------------------------------------------
__global__ void __launch_bounds__(256) k_agg128(
    const float* __restrict__ H, const float* __restrict__ bias,
    float* __restrict__ OUT, int n)
{
    int node = blockIdx.x * 8 + (threadIdx.x >> 5);
    if (node >= n) return;
    int lane = threadIdx.x & 31;

    int beg = g_rowptr[node];
    int end = beg + g_deg[node];

    float4 acc = make_float4(0.f, 0.f, 0.f, 0.f);
    int j = beg;
    for (; j + 4 <= end; j += 4) {
        int s0 = g_csrc[j], s1 = g_csrc[j + 1];
        int s2 = g_csrc[j + 2], s3 = g_csrc[j + 3];
        float w0 = g_dinv[s0], w1 = g_dinv[s1];
        float w2 = g_dinv[s2], w3 = g_dinv[s3];
        float4 v0 = *(const float4*)&H[(size_t)s0 * 128 + lane * 4];
        float4 v1 = *(const float4*)&H[(size_t)s1 * 128 + lane * 4];
        float4 v2 = *(const float4*)&H[(size_t)s2 * 128 + lane * 4];
        float4 v3 = *(const float4*)&H[(size_t)s3 * 128 + lane * 4];
        acc.x += w0 * v0.x + w1 * v1.x + w2 * v2.x + w3 * v3.x;
        acc.y += w0 * v0.y + w1 * v1.y + w2 * v2.y + w3 * v3.y;
        acc.z += w0 * v0.z + w1 * v1.z + w2 * v2.z + w3 * v3.z;
        acc.w += w0 * v0.w + w1 * v1.w + w2 * v2.w + w3 * v3.w;
    }
    for (; j < end; j++) {
        int s = g_csrc[j];
        float w = g_dinv[s];
        float4 v = *(const float4*)&H[(size_t)s * 128 + lane * 4];
        acc.x += w * v.x; acc.y += w * v.y;
        acc.z += w * v.z; acc.w += w * v.w;
    }

    float di = g_dinv[node];
    float4 hs = *(const float4*)&H[(size_t)node * 128 + lane * 4];
    float4 bb = *(const float4*)&bias[lane * 4];
    float4 o;
    o.x = bb.x + di * (acc.x + di * hs.x);
    o.y = bb.y + di * (acc.y + di * hs.y);
    o.z = bb.z + di * (acc.z + di * hs.z);
    o.w = bb.w + di * (acc.w + di * hs.w);
    *(float4*)&OUT[(size_t)node * 128 + lane * 4] = o;
}

__global__ void __launch_bounds__(256) k_agg64(
    const float* __restrict__ H, const float* __restrict__ bias,
    float* __restrict__ OUT, int n)
{
    int node = blockIdx.x * 8 + (threadIdx.x >> 5);
    if (node >= n) return;
    int lane = threadIdx.x & 31;

    int beg = g_rowptr[node];
    int end = beg + g_deg[node];

    float2 acc = make_float2(0.f, 0.f);
    int j = beg;
    for (; j + 4 <= end; j += 4) {
        int s0 = g_csrc[j], s1 = g_csrc[j + 1];
        int s2 = g_csrc[j + 2], s3 = g_csrc[j + 3];
        float w0 = g_dinv[s0], w1 = g_dinv[s1];
        float w2 = g_dinv[s2], w3 = g_dinv[s3];
        float2 v0 = *(const float2*)&H[(size_t)s0 * 64 + lane * 2];
        float2 v1 = *(const float2*)&H[(size_t)s1 * 64 + lane * 2];
        float2 v2 = *(const float2*)&H[(size_t)s2 * 64 + lane * 2];
        float2 v3 = *(const float2*)&H[(size_t)s3 * 64 + lane * 2];
        acc.x += w0 * v0.x + w1 * v1.x + w2 * v2.x + w3 * v3.x;
        acc.y += w0 * v0.y + w1 * v1.y + w2 * v2.y + w3 * v3.y;
    }
    for (; j < end; j++) {
        int s = g_csrc[j];
        float w = g_dinv[s];
        float2 v = *(const float2*)&H[(size_t)s * 64 + lane * 2];
        acc.x += w * v.x; acc.y += w * v.y;
    }

    float di = g_dinv[node];
    float2 hs = *(const float2*)&H[(size_t)node * 64 + lane * 2];
    float2 bb = *(const float2*)&bias[lane * 2];
    float2 o;
    o.x = bb.x + di * (acc.x + di * hs.x);
    o.y = bb.y + di * (acc.y + di * hs.y);
    *(float2*)&OUT[(size_t)node * 64 + lane * 2] = o;         // mu
    *(float2*)&OUT[(size_t)(n + node) * 64 + lane * 2] = o;   // logstd
}

// ---------------------------------------------------------------------------
extern "C" void kernel_launch(void* const* d_in, const int* in_sizes, int n_in,
                              void* d_out, int out_size)
{
    const float* x  = (const float*)d_in[0];
    const float* W1 = (const float*)d_in[1];
    const float* b1 = (const float*)d_in[2];
    const float* W2 = (const float*)d_in[3];
    const float* b2 = (const float*)d_in[4];
    const float* W3 = (const float*)d_in[5];
    const float* b3 = (const float*)d_in[6];
    const void*  ei = d_in[7];

    int n = in_sizes[0] / DIN;
    int e = in_sizes[7] / 2;
    float* out = (float*)d_out;

    float *bufA, *bufB;
    cudaGetSymbolAddress((void**)&bufA, g_bufA);
    cudaGetSymbolAddress((void**)&bufB, g_bufB);
    __nv_bfloat16 *wh, *wl;
    cudaGetSymbolAddress((void**)&wh, g_wh);
    cudaGetSymbolAddress((void**)&wl, g_wl);

    constexpr int RS = 136;
    const int SMEM128 = (8 * 16 * RS * 2 + 128 * RS * 2) * 2;  // ~136 KB
    const int SMEM64  = (8 * 16 * RS * 2 + 64 * RS * 2) * 2;   // ~102 KB
    cudaFuncSetAttribute(k_mma<128, false>,
                         cudaFuncAttributeMaxDynamicSharedMemorySize, SMEM128);
    cudaFuncSetAttribute(k_mma<128, true>,
                         cudaFuncAttributeMaxDynamicSharedMemorySize, SMEM128);
    cudaFuncSetAttribute(k_mma<64, true>,
                         cudaFuncAttributeMaxDynamicSharedMemorySize, SMEM64);

    int nb  = (n + 255) / 256;
    int ebk = (e + 255) / 256;
    int nsb = (n + 1023) / 1024;

    // --- edge conversion + CSR build + normalization + weight split ---
    k_probe_init<<<1, 1>>>();
    k_probe<<<ebk, 256>>>((const long long*)ei, e, n);
    k_zero_deg<<<nb, 256>>>(n);
    k_convert_hist<<<ebk, 256>>>(ei, e);
    k_scan1<<<nsb, 1024>>>(n);
    k_scan2<<<1, 128>>>(nsb);
    k_scan3<<<nb, 256>>>(n);
    k_fill<<<ebk, 256>>>(e);
    k_prep_w<<<160, 256>>>(W1, W2, W3);

    int gb = (n + 127) / 128;   // GEMM tiles
    int ag = (n + 7) / 8;       // agg blocks

    // Layer 1
    k_mma<128, false><<<gb, 256, SMEM128>>>(x, wh, wl, bufA, n);
    k_agg128<<<ag, 256>>>(bufA, b1, bufB, n);
    // Layer 2
    k_mma<128, true><<<gb, 256, SMEM128>>>(bufB, wh + 16384, wl + 16384, bufA, n);
    k_agg128<<<ag, 256>>>(bufA, b2, bufB, n);
    // Layer 3 (FOUT=64) -> mu & logstd
    k_mma<64, true><<<gb, 256, SMEM64>>>(bufB, wh + 32768, wl + 32768, bufA, n);
    k_agg64<<<ag, 256>>>(bufA, b3, out, n);
}